// round 3
// baseline (speedup 1.0000x reference)
#include <cuda_runtime.h>

#define NN 100000
#define EE 1600000
#define DD 64
#define LL 3
#define EPS 1e-5f

// ---------------- device scratch (no allocations allowed) ----------------
__device__ int   g_deg[NN];        // degree incl. self loop
__device__ float g_dinv[NN];       // rsqrt(deg)
__device__ int   g_off[NN + 1];    // CSR offsets (edges only, by target)
__device__ int   g_cursor[NN];     // fill cursors
__device__ int   g_src[EE];        // CSR: source node per edge
__device__ float g_wgt[EE];        // CSR: dinv[src]*dinv[dst]
__device__ float g_hw[NN * DD];    // h @ W buffer
__device__ float g_h[NN * DD];     // intermediate h buffer

// ---------------- CSR build ----------------
__global__ __launch_bounds__(256) void k_init_deg() {
    int i = blockIdx.x * blockDim.x + threadIdx.x;
    if (i < NN) g_deg[i] = 1;  // self loop
}

__global__ __launch_bounds__(256) void k_count(const int* __restrict__ ei) {
    int e = blockIdx.x * blockDim.x + threadIdx.x;
    if (e < EE) atomicAdd(&g_deg[ei[EE + e]], 1);
}

// single-block exclusive scan of (deg-1) -> g_off, 256 threads
__global__ __launch_bounds__(256) void k_scan() {
    __shared__ int ssum[256];
    const int t = threadIdx.x;
    const int C = (NN + 255) / 256;  // 391 elems per thread
    const int base = t * C;
    int s = 0;
    for (int i = 0; i < C; i++) {
        int idx = base + i;
        if (idx < NN) s += g_deg[idx] - 1;
    }
    ssum[t] = s;
    __syncthreads();
    // Hillis-Steele inclusive scan over 256 partials
    for (int off = 1; off < 256; off <<= 1) {
        int v = (t >= off) ? ssum[t - off] : 0;
        __syncthreads();
        ssum[t] += v;
        __syncthreads();
    }
    int run = (t == 0) ? 0 : ssum[t - 1];
    for (int i = 0; i < C; i++) {
        int idx = base + i;
        if (idx < NN) {
            g_off[idx] = run;
            run += g_deg[idx] - 1;
        }
    }
    if (t == 255) g_off[NN] = ssum[255];
}

__global__ __launch_bounds__(256) void k_prep() {
    int i = blockIdx.x * blockDim.x + threadIdx.x;
    if (i < NN) {
        g_dinv[i] = rsqrtf((float)g_deg[i]);
        g_cursor[i] = g_off[i];
    }
}

__global__ __launch_bounds__(256) void k_fill(const int* __restrict__ ei) {
    int e = blockIdx.x * blockDim.x + threadIdx.x;
    if (e < EE) {
        int r = ei[e];
        int c = ei[EE + e];
        int p = atomicAdd(&g_cursor[c], 1);
        g_src[p] = r;
        g_wgt[p] = g_dinv[r] * g_dinv[c];
    }
}

// ---------------- GEMM: hw = hin @ W (N x 64 @ 64 x 64) ----------------
// block = 256 threads = 16 rows x 16 lane-groups; each thread computes 4 cols
__global__ __launch_bounds__(256) void k_gemm(const float* __restrict__ hin,
                                              const float* __restrict__ W,
                                              float* __restrict__ hout) {
    __shared__ float4 sW[64][16];     // W[k][4j..4j+3]
    __shared__ float  sH[16][64];     // 16 input rows

    const int t = threadIdx.x;
    // load W (4096 floats = 1024 float4, 4 per thread)
    const float4* W4 = (const float4*)W;
    for (int i = t; i < 1024; i += 256) ((float4*)sW)[i] = W4[i];

    const int r = t >> 4;       // 0..15 local row
    const int j = t & 15;       // 0..15 col group
    const int row = blockIdx.x * 16 + r;

    float4 hv = make_float4(0.f, 0.f, 0.f, 0.f);
    if (row < NN) hv = ((const float4*)hin)[row * 16 + j];
    ((float4*)&sH[r][0])[j] = hv;
    __syncthreads();

    float4 acc = make_float4(0.f, 0.f, 0.f, 0.f);
#pragma unroll
    for (int k = 0; k < 64; k++) {
        float a = sH[r][k];
        float4 w = sW[k][j];
        acc.x += a * w.x;
        acc.y += a * w.y;
        acc.z += a * w.z;
        acc.w += a * w.w;
    }
    if (row < NN) ((float4*)hout)[row * 16 + j] = acc;
}

// ---------------- fused aggregate + bias + LayerNorm (+ReLU) ----------------
// 16 lanes per node, each lane owns a float4 column chunk
__global__ __launch_bounds__(256) void k_agg(const float* __restrict__ hw,
                                             const float* __restrict__ bias,
                                             const float* __restrict__ gamma,
                                             const float* __restrict__ beta,
                                             float* __restrict__ out,
                                             int do_relu) {
    const int t = threadIdx.x;
    const int node = blockIdx.x * 16 + (t >> 4);
    const int j = t & 15;
    if (node >= NN) return;

    const float4* hw4 = (const float4*)hw;

    // self-loop term
    float dn = g_dinv[node];
    float4 acc = hw4[node * 16 + j];
    float wself = dn * dn;
    acc.x *= wself; acc.y *= wself; acc.z *= wself; acc.w *= wself;

    int p = g_off[node];
    const int pend = g_off[node + 1];
    for (; p < pend; p++) {
        int src = __ldg(&g_src[p]);
        float w = __ldg(&g_wgt[p]);
        float4 v = hw4[src * 16 + j];
        acc.x += w * v.x;
        acc.y += w * v.y;
        acc.z += w * v.z;
        acc.w += w * v.w;
    }

    // bias
    float4 b = ((const float4*)bias)[j];
    acc.x += b.x; acc.y += b.y; acc.z += b.z; acc.w += b.w;

    // LayerNorm over 64 values (16 lanes x 4)
    float lsum = acc.x + acc.y + acc.z + acc.w;
    float lsq  = acc.x * acc.x + acc.y * acc.y + acc.z * acc.z + acc.w * acc.w;
#pragma unroll
    for (int m = 8; m >= 1; m >>= 1) {
        lsum += __shfl_xor_sync(0xffffffffu, lsum, m, 16);
        lsq  += __shfl_xor_sync(0xffffffffu, lsq,  m, 16);
    }
    float mean = lsum * (1.0f / 64.0f);
    float var = lsq * (1.0f / 64.0f) - mean * mean;
    float rstd = rsqrtf(var + EPS);

    float4 g = ((const float4*)gamma)[j];
    float4 be = ((const float4*)beta)[j];
    float4 o;
    o.x = (acc.x - mean) * rstd * g.x + be.x;
    o.y = (acc.y - mean) * rstd * g.y + be.y;
    o.z = (acc.z - mean) * rstd * g.z + be.z;
    o.w = (acc.w - mean) * rstd * g.w + be.w;
    if (do_relu) {
        o.x = fmaxf(o.x, 0.f);
        o.y = fmaxf(o.y, 0.f);
        o.z = fmaxf(o.z, 0.f);
        o.w = fmaxf(o.w, 0.f);
    }
    ((float4*)out)[node * 16 + j] = o;
}

// ---------------- launch ----------------
extern "C" void kernel_launch(void* const* d_in, const int* in_sizes, int n_in,
                              void* d_out, int out_size) {
    const float* x      = (const float*)d_in[0];   // (N, D)
    const float* Ws     = (const float*)d_in[1];   // (L, D, D)
    const float* bs     = (const float*)d_in[2];   // (L, D)
    const float* gammas = (const float*)d_in[3];   // (L, D)
    const float* betas  = (const float*)d_in[4];   // (L, D)
    const int*   ei     = (const int*)d_in[5];     // (2, E)
    float* outp = (float*)d_out;

    float* d_hw;
    float* d_h;
    cudaGetSymbolAddress((void**)&d_hw, g_hw);
    cudaGetSymbolAddress((void**)&d_h, g_h);

    const int TB = 256;
    const int gN = (NN + TB - 1) / TB;
    const int gE = (EE + TB - 1) / TB;
    const int gNode = (NN + 15) / 16;

    // CSR build (once per launch, shared by all layers)
    k_init_deg<<<gN, TB>>>();
    k_count<<<gE, TB>>>(ei);
    k_scan<<<1, 256>>>();
    k_prep<<<gN, TB>>>();
    k_fill<<<gE, TB>>>(ei);

    // layer 0: x -> g_h
    k_gemm<<<gNode, TB>>>(x, Ws + 0 * DD * DD, d_hw);
    k_agg<<<gNode, TB>>>(d_hw, bs + 0 * DD, gammas + 0 * DD, betas + 0 * DD, d_h, 1);
    // layer 1: g_h -> g_h
    k_gemm<<<gNode, TB>>>(d_h, Ws + 1 * DD * DD, d_hw);
    k_agg<<<gNode, TB>>>(d_hw, bs + 1 * DD, gammas + 1 * DD, betas + 1 * DD, d_h, 1);
    // layer 2: g_h -> out (no relu)
    k_gemm<<<gNode, TB>>>(d_h, Ws + 2 * DD * DD, d_hw);
    k_agg<<<gNode, TB>>>(d_hw, bs + 2 * DD, gammas + 2 * DD, betas + 2 * DD, outp, 0);
}

// round 4
// speedup vs baseline: 1.4278x; 1.4278x over previous
#include <cuda_runtime.h>

#define NN 100000
#define EE 1600000
#define DD 64
#define EPS 1e-5f

#define NBLK 98                       // ceil(NN/1024)
#define NN_PAD (NBLK * 1024)          // 100352

// ---------------- device scratch (no allocations allowed) ----------------
__device__ __align__(16) int   g_deg[NN_PAD];      // edge count per target (no self loop)
__device__ __align__(16) float g_dinv[NN_PAD];     // rsqrt(deg+1)
__device__ __align__(16) int   g_off[NN_PAD];      // CSR offsets; g_off[NN]=EE via padding
__device__ __align__(16) int   g_cursor[NN_PAD];   // fill cursors
__device__                int   g_bsum[NBLK];      // per-block sums
__device__                int   g_bpre[NBLK];      // per-block exclusive prefix
__device__ __align__(8)  int2  g_edge[EE];         // (src, float-bits weight)
__device__ __align__(16) float g_hw[NN * DD];      // h @ W buffer
__device__ __align__(16) float g_h[NN * DD];       // intermediate h buffer

// ---------------- CSR build ----------------
__global__ __launch_bounds__(256) void k_count(const int* __restrict__ ei) {
    int e = blockIdx.x * blockDim.x + threadIdx.x;
    if (e < EE) atomicAdd(&g_deg[ei[EE + e]], 1);
}

// pass 1: per-block (1024 elems) sums, coalesced int4 loads
__global__ __launch_bounds__(256) void k_bsum() {
    const int t = threadIdx.x, b = blockIdx.x;
    const int4* d4 = (const int4*)g_deg;
    int4 v = d4[b * 256 + t];
    int s = v.x + v.y + v.z + v.w;
#pragma unroll
    for (int m = 16; m; m >>= 1) s += __shfl_xor_sync(0xffffffffu, s, m);
    __shared__ int ws[8];
    if ((t & 31) == 0) ws[t >> 5] = s;
    __syncthreads();
    if (t == 0) {
        int x = 0;
#pragma unroll
        for (int i = 0; i < 8; i++) x += ws[i];
        g_bsum[b] = x;
    }
}

// pass 2: exclusive scan of the 98 block sums (1 block, 128 threads)
__global__ __launch_bounds__(128) void k_bscan() {
    __shared__ int s[128];
    const int t = threadIdx.x;
    int v = (t < NBLK) ? g_bsum[t] : 0;
    s[t] = v;
    __syncthreads();
    for (int off = 1; off < 128; off <<= 1) {
        int u = (t >= off) ? s[t - off] : 0;
        __syncthreads();
        s[t] += u;
        __syncthreads();
    }
    if (t < NBLK) g_bpre[t] = s[t] - v;  // exclusive
}

// pass 3: per-block rescan; writes g_off, g_cursor, g_dinv (all coalesced, padded)
__global__ __launch_bounds__(256) void k_bscan_fill() {
    const int t = threadIdx.x, b = blockIdx.x;
    const int lane = t & 31, wid = t >> 5;
    const int4* d4 = (const int4*)g_deg;
    int4 c = d4[b * 256 + t];
    int sum4 = c.x + c.y + c.z + c.w;

    // inclusive warp scan of per-thread sums
    int inc = sum4;
#pragma unroll
    for (int m = 1; m < 32; m <<= 1) {
        int u = __shfl_up_sync(0xffffffffu, inc, m);
        if (lane >= m) inc += u;
    }
    __shared__ int wsum[8], wpre[8];
    if (lane == 31) wsum[wid] = inc;
    __syncthreads();
    if (t == 0) {
        int r = 0;
#pragma unroll
        for (int i = 0; i < 8; i++) { wpre[i] = r; r += wsum[i]; }
    }
    __syncthreads();

    int excl = inc - sum4 + wpre[wid] + g_bpre[b];
    int o0 = excl, o1 = o0 + c.x, o2 = o1 + c.y, o3 = o2 + c.z;
    int4 off4 = make_int4(o0, o1, o2, o3);
    ((int4*)g_off)[b * 256 + t] = off4;
    ((int4*)g_cursor)[b * 256 + t] = off4;
    float4 dv;
    dv.x = rsqrtf((float)(c.x + 1));
    dv.y = rsqrtf((float)(c.y + 1));
    dv.z = rsqrtf((float)(c.z + 1));
    dv.w = rsqrtf((float)(c.w + 1));
    ((float4*)g_dinv)[b * 256 + t] = dv;
}

__global__ __launch_bounds__(256) void k_fill(const int* __restrict__ ei) {
    int e = blockIdx.x * blockDim.x + threadIdx.x;
    if (e < EE) {
        int r = ei[e];
        int c = ei[EE + e];
        int p = atomicAdd(&g_cursor[c], 1);
        float w = g_dinv[r] * g_dinv[c];
        g_edge[p] = make_int2(r, __float_as_int(w));
    }
}

// ---------------- GEMM: hw = hin @ W (N x 64 @ 64 x 64) ----------------
__global__ __launch_bounds__(256) void k_gemm(const float* __restrict__ hin,
                                              const float* __restrict__ W,
                                              float* __restrict__ hout) {
    __shared__ float4 sW[64][16];
    __shared__ float  sH[16][64];

    const int t = threadIdx.x;
    const float4* W4 = (const float4*)W;
    for (int i = t; i < 1024; i += 256) ((float4*)sW)[i] = W4[i];

    const int r = t >> 4;
    const int j = t & 15;
    const int row = blockIdx.x * 16 + r;

    float4 hv = make_float4(0.f, 0.f, 0.f, 0.f);
    if (row < NN) hv = ((const float4*)hin)[row * 16 + j];
    ((float4*)&sH[r][0])[j] = hv;
    __syncthreads();

    float4 acc = make_float4(0.f, 0.f, 0.f, 0.f);
#pragma unroll
    for (int k = 0; k < 64; k++) {
        float a = sH[r][k];
        float4 w = sW[k][j];
        acc.x += a * w.x;
        acc.y += a * w.y;
        acc.z += a * w.z;
        acc.w += a * w.w;
    }
    if (row < NN) ((float4*)hout)[row * 16 + j] = acc;
}

// ---------------- fused aggregate + bias + LayerNorm (+ReLU) ----------------
__global__ __launch_bounds__(256) void k_agg(const float* __restrict__ hw,
                                             const float* __restrict__ bias,
                                             const float* __restrict__ gamma,
                                             const float* __restrict__ beta,
                                             float* __restrict__ out,
                                             int do_relu) {
    const int t = threadIdx.x;
    const int node = blockIdx.x * 16 + (t >> 4);
    const int j = t & 15;
    if (node >= NN) return;

    const float4* hw4 = (const float4*)hw;

    // self-loop term
    float dn = g_dinv[node];
    float4 acc = hw4[node * 16 + j];
    float wself = dn * dn;
    acc.x *= wself; acc.y *= wself; acc.z *= wself; acc.w *= wself;

    int p = g_off[node];
    const int pend = g_off[node + 1];
    // unroll x2 for MLP on the 2-level pointer chase
    for (; p + 1 < pend; p += 2) {
        int2 e0 = __ldg(&g_edge[p]);
        int2 e1 = __ldg(&g_edge[p + 1]);
        float w0 = __int_as_float(e0.y);
        float w1 = __int_as_float(e1.y);
        float4 v0 = hw4[e0.x * 16 + j];
        float4 v1 = hw4[e1.x * 16 + j];
        acc.x += w0 * v0.x + w1 * v1.x;
        acc.y += w0 * v0.y + w1 * v1.y;
        acc.z += w0 * v0.z + w1 * v1.z;
        acc.w += w0 * v0.w + w1 * v1.w;
    }
    if (p < pend) {
        int2 e0 = __ldg(&g_edge[p]);
        float w0 = __int_as_float(e0.y);
        float4 v0 = hw4[e0.x * 16 + j];
        acc.x += w0 * v0.x;
        acc.y += w0 * v0.y;
        acc.z += w0 * v0.z;
        acc.w += w0 * v0.w;
    }

    float4 b = ((const float4*)bias)[j];
    acc.x += b.x; acc.y += b.y; acc.z += b.z; acc.w += b.w;

    // LayerNorm over 64 values (16 lanes x 4)
    float lsum = acc.x + acc.y + acc.z + acc.w;
    float lsq  = acc.x * acc.x + acc.y * acc.y + acc.z * acc.z + acc.w * acc.w;
#pragma unroll
    for (int m = 8; m >= 1; m >>= 1) {
        lsum += __shfl_xor_sync(0xffffffffu, lsum, m, 16);
        lsq  += __shfl_xor_sync(0xffffffffu, lsq,  m, 16);
    }
    float mean = lsum * (1.0f / 64.0f);
    float var = lsq * (1.0f / 64.0f) - mean * mean;
    float rstd = rsqrtf(var + EPS);

    float4 g = ((const float4*)gamma)[j];
    float4 be = ((const float4*)beta)[j];
    float4 o;
    o.x = (acc.x - mean) * rstd * g.x + be.x;
    o.y = (acc.y - mean) * rstd * g.y + be.y;
    o.z = (acc.z - mean) * rstd * g.z + be.z;
    o.w = (acc.w - mean) * rstd * g.w + be.w;
    if (do_relu) {
        o.x = fmaxf(o.x, 0.f);
        o.y = fmaxf(o.y, 0.f);
        o.z = fmaxf(o.z, 0.f);
        o.w = fmaxf(o.w, 0.f);
    }
    ((float4*)out)[node * 16 + j] = o;
}

// ---------------- launch ----------------
extern "C" void kernel_launch(void* const* d_in, const int* in_sizes, int n_in,
                              void* d_out, int out_size) {
    const float* x      = (const float*)d_in[0];   // (N, D)
    const float* Ws     = (const float*)d_in[1];   // (L, D, D)
    const float* bs     = (const float*)d_in[2];   // (L, D)
    const float* gammas = (const float*)d_in[3];   // (L, D)
    const float* betas  = (const float*)d_in[4];   // (L, D)
    const int*   ei     = (const int*)d_in[5];     // (2, E)
    float* outp = (float*)d_out;

    float* d_hw;
    float* d_h;
    void*  d_deg;
    cudaGetSymbolAddress((void**)&d_hw, g_hw);
    cudaGetSymbolAddress((void**)&d_h, g_h);
    cudaGetSymbolAddress(&d_deg, g_deg);

    const int TB = 256;
    const int gE = (EE + TB - 1) / TB;
    const int gNode = (NN + 15) / 16;

    // CSR build (once per launch, shared by all layers)
    cudaMemsetAsync(d_deg, 0, NN_PAD * sizeof(int));
    k_count<<<gE, TB>>>(ei);
    k_bsum<<<NBLK, 256>>>();
    k_bscan<<<1, 128>>>();
    k_bscan_fill<<<NBLK, 256>>>();
    k_fill<<<gE, TB>>>(ei);

    // layer 0: x -> g_h
    k_gemm<<<gNode, TB>>>(x, Ws + 0 * DD * DD, d_hw);
    k_agg<<<gNode, TB>>>(d_hw, bs + 0 * DD, gammas + 0 * DD, betas + 0 * DD, d_h, 1);
    // layer 1: g_h -> g_h
    k_gemm<<<gNode, TB>>>(d_h, Ws + 1 * DD * DD, d_hw);
    k_agg<<<gNode, TB>>>(d_hw, bs + 1 * DD, gammas + 1 * DD, betas + 1 * DD, d_h, 1);
    // layer 2: g_h -> out (no relu)
    k_gemm<<<gNode, TB>>>(d_h, Ws + 2 * DD * DD, d_hw);
    k_agg<<<gNode, TB>>>(d_hw, bs + 2 * DD, gammas + 2 * DD, betas + 2 * DD, outp, 0);
}

// round 7
// speedup vs baseline: 1.9914x; 1.3947x over previous
#include <cuda_runtime.h>

#define NN 100000
#define EE 1600000
#define DD 64
#define EPS 1e-5f

#define NBLK 98                       // ceil(NN/1024)
#define NN_PAD (NBLK * 1024)          // 100352

// ---------------- device scratch (no allocations allowed) ----------------
__device__ __align__(16) int   g_deg[NN_PAD];      // edge count per target (no self loop)
__device__ __align__(16) float g_dinv[NN_PAD];     // rsqrt(deg+1)
__device__ __align__(16) int   g_off[NN_PAD];      // CSR offsets; g_off[NN]=EE via padding
__device__ __align__(16) int   g_cursor[NN_PAD];   // fill cursors
__device__                int   g_bsum[NBLK];      // per-block sums
__device__                int   g_bpre[NBLK];      // per-block exclusive prefix
__device__ __align__(8)  int2  g_edge[EE];         // (src, float-bits weight)
__device__ __align__(16) float g_hw[NN * DD];      // h @ W buffer
__device__ __align__(16) float g_h[NN * DD];       // intermediate h buffer

// ---------------- CSR build ----------------
__global__ __launch_bounds__(256) void k_count(const int* __restrict__ ei) {
    int e = blockIdx.x * blockDim.x + threadIdx.x;
    if (e < EE) atomicAdd(&g_deg[ei[EE + e]], 1);
}

// pass 1: per-block (1024 elems) sums, coalesced int4 loads
__global__ __launch_bounds__(256) void k_bsum() {
    const int t = threadIdx.x, b = blockIdx.x;
    const int4* d4 = (const int4*)g_deg;
    int4 v = d4[b * 256 + t];
    int s = v.x + v.y + v.z + v.w;
#pragma unroll
    for (int m = 16; m; m >>= 1) s += __shfl_xor_sync(0xffffffffu, s, m);
    __shared__ int ws[8];
    if ((t & 31) == 0) ws[t >> 5] = s;
    __syncthreads();
    if (t == 0) {
        int x = 0;
#pragma unroll
        for (int i = 0; i < 8; i++) x += ws[i];
        g_bsum[b] = x;
    }
}

// pass 2: exclusive scan of the 98 block sums (1 block, 128 threads)
__global__ __launch_bounds__(128) void k_bscan() {
    __shared__ int s[128];
    const int t = threadIdx.x;
    int v = (t < NBLK) ? g_bsum[t] : 0;
    s[t] = v;
    __syncthreads();
    for (int off = 1; off < 128; off <<= 1) {
        int u = (t >= off) ? s[t - off] : 0;
        __syncthreads();
        s[t] += u;
        __syncthreads();
    }
    if (t < NBLK) g_bpre[t] = s[t] - v;  // exclusive
}

// pass 3: per-block rescan; writes g_off, g_cursor, g_dinv (all coalesced, padded)
__global__ __launch_bounds__(256) void k_bscan_fill() {
    const int t = threadIdx.x, b = blockIdx.x;
    const int lane = t & 31, wid = t >> 5;
    const int4* d4 = (const int4*)g_deg;
    int4 c = d4[b * 256 + t];
    int sum4 = c.x + c.y + c.z + c.w;

    // inclusive warp scan of per-thread sums
    int inc = sum4;
#pragma unroll
    for (int m = 1; m < 32; m <<= 1) {
        int u = __shfl_up_sync(0xffffffffu, inc, m);
        if (lane >= m) inc += u;
    }
    __shared__ int wsum[8], wpre[8];
    if (lane == 31) wsum[wid] = inc;
    __syncthreads();
    if (t == 0) {
        int r = 0;
#pragma unroll
        for (int i = 0; i < 8; i++) { wpre[i] = r; r += wsum[i]; }
    }
    __syncthreads();

    int excl = inc - sum4 + wpre[wid] + g_bpre[b];
    int o0 = excl, o1 = o0 + c.x, o2 = o1 + c.y, o3 = o2 + c.z;
    int4 off4 = make_int4(o0, o1, o2, o3);
    ((int4*)g_off)[b * 256 + t] = off4;
    ((int4*)g_cursor)[b * 256 + t] = off4;
    float4 dv;
    dv.x = rsqrtf((float)(c.x + 1));
    dv.y = rsqrtf((float)(c.y + 1));
    dv.z = rsqrtf((float)(c.z + 1));
    dv.w = rsqrtf((float)(c.w + 1));
    ((float4*)g_dinv)[b * 256 + t] = dv;
}

__global__ __launch_bounds__(256) void k_fill(const int* __restrict__ ei) {
    int e = blockIdx.x * blockDim.x + threadIdx.x;
    if (e < EE) {
        int r = ei[e];
        int c = ei[EE + e];
        int p = atomicAdd(&g_cursor[c], 1);
        float w = g_dinv[r] * g_dinv[c];
        g_edge[p] = make_int2(r, __float_as_int(w));
    }
}

// ---------------- GEMM: hw = hin @ W (N x 64 @ 64 x 64) ----------------
// 64 rows per block of 256 threads; each thread: 4 rows x 4 cols register tile
__global__ __launch_bounds__(256) void k_gemm(const float* __restrict__ hin,
                                              const float* __restrict__ W,
                                              float* __restrict__ hout) {
    __shared__ float4 sW[64 * 16];     // W[k][j4]
    __shared__ float  sH[64][68];      // 68-pad: kills half-warp row bank conflict

    const int t = threadIdx.x;
    const float4* W4 = (const float4*)W;
#pragma unroll
    for (int i = 0; i < 4; i++) sW[t + i * 256] = W4[t + i * 256];

    const int rowbase = blockIdx.x * 64;
    const float4* hin4 = (const float4*)hin;
#pragma unroll
    for (int i = 0; i < 4; i++) {
        int idx = t + i * 256;          // 0..1023
        int r = idx >> 4, c = idx & 15;
        float4 v = make_float4(0.f, 0.f, 0.f, 0.f);
        if (rowbase + r < NN) v = hin4[(rowbase + r) * 16 + c];
        ((float4*)&sH[r][0])[c] = v;
    }
    __syncthreads();

    const int j = t & 15;       // col group (4 cols)
    const int rg = t >> 4;      // row within 16-row band; rows rg, rg+16, rg+32, rg+48

    float4 a0 = make_float4(0.f, 0.f, 0.f, 0.f);
    float4 a1 = a0, a2 = a0, a3 = a0;
#pragma unroll 16
    for (int k = 0; k < 64; k++) {
        float4 w = sW[k * 16 + j];
        float h0 = sH[rg][k];
        float h1 = sH[rg + 16][k];
        float h2 = sH[rg + 32][k];
        float h3 = sH[rg + 48][k];
        a0.x += h0 * w.x; a0.y += h0 * w.y; a0.z += h0 * w.z; a0.w += h0 * w.w;
        a1.x += h1 * w.x; a1.y += h1 * w.y; a1.z += h1 * w.z; a1.w += h1 * w.w;
        a2.x += h2 * w.x; a2.y += h2 * w.y; a2.z += h2 * w.z; a2.w += h2 * w.w;
        a3.x += h3 * w.x; a3.y += h3 * w.y; a3.z += h3 * w.z; a3.w += h3 * w.w;
    }

    float4* hout4 = (float4*)hout;
    if (rowbase + rg < NN)      hout4[(rowbase + rg) * 16 + j] = a0;
    if (rowbase + rg + 16 < NN) hout4[(rowbase + rg + 16) * 16 + j] = a1;
    if (rowbase + rg + 32 < NN) hout4[(rowbase + rg + 32) * 16 + j] = a2;
    if (rowbase + rg + 48 < NN) hout4[(rowbase + rg + 48) * 16 + j] = a3;
}

// ---------------- fused aggregate + bias + LayerNorm (+ReLU) ----------------
// 16 lanes per node; edge metadata loaded 16-at-a-time cooperatively + shfl broadcast
__global__ __launch_bounds__(256) void k_agg(const float* __restrict__ hw,
                                             const float* __restrict__ bias,
                                             const float* __restrict__ gamma,
                                             const float* __restrict__ beta,
                                             float* __restrict__ out,
                                             int do_relu) {
    const int t = threadIdx.x;
    const int node = blockIdx.x * 16 + (t >> 4);   // NN % 16 == 0: always valid
    const int j = t & 15;
    const unsigned gmask = 0xffffu << (t & 16);    // this half-warp's lanes

    const float4* hw4 = (const float4*)hw;

    // self-loop term
    float dn = g_dinv[node];
    float4 acc = hw4[node * 16 + j];
    float wself = dn * dn;
    acc.x *= wself; acc.y *= wself; acc.z *= wself; acc.w *= wself;

    int p = g_off[node];
    const int pend = g_off[node + 1];

    // full batches of 16 edges: one coalesced meta load, shfl-broadcast each
    while (p + 16 <= pend) {
        int2 e = __ldg(&g_edge[p + j]);
#pragma unroll
        for (int i = 0; i < 16; i++) {
            int src = __shfl_sync(gmask, e.x, i, 16);
            float w = __int_as_float(__shfl_sync(gmask, e.y, i, 16));
            float4 v = hw4[src * 16 + j];
            acc.x += w * v.x;
            acc.y += w * v.y;
            acc.z += w * v.z;
            acc.w += w * v.w;
        }
        p += 16;
    }
    // remainder (0..15 edges)
    int rem = pend - p;
    if (rem > 0) {
        int2 e = make_int2(0, 0);
        if (j < rem) e = __ldg(&g_edge[p + j]);
        for (int i = 0; i < rem; i++) {
            int src = __shfl_sync(gmask, e.x, i, 16);
            float w = __int_as_float(__shfl_sync(gmask, e.y, i, 16));
            float4 v = hw4[src * 16 + j];
            acc.x += w * v.x;
            acc.y += w * v.y;
            acc.z += w * v.z;
            acc.w += w * v.w;
        }
    }

    float4 b = ((const float4*)bias)[j];
    acc.x += b.x; acc.y += b.y; acc.z += b.z; acc.w += b.w;

    // LayerNorm over 64 values (16 lanes x 4)
    float lsum = acc.x + acc.y + acc.z + acc.w;
    float lsq  = acc.x * acc.x + acc.y * acc.y + acc.z * acc.z + acc.w * acc.w;
#pragma unroll
    for (int m = 8; m >= 1; m >>= 1) {
        lsum += __shfl_xor_sync(gmask, lsum, m, 16);
        lsq  += __shfl_xor_sync(gmask, lsq,  m, 16);
    }
    float mean = lsum * (1.0f / 64.0f);
    float var = lsq * (1.0f / 64.0f) - mean * mean;
    float rstd = rsqrtf(var + EPS);

    float4 g = ((const float4*)gamma)[j];
    float4 be = ((const float4*)beta)[j];
    float4 o;
    o.x = (acc.x - mean) * rstd * g.x + be.x;
    o.y = (acc.y - mean) * rstd * g.y + be.y;
    o.z = (acc.z - mean) * rstd * g.z + be.z;
    o.w = (acc.w - mean) * rstd * g.w + be.w;
    if (do_relu) {
        o.x = fmaxf(o.x, 0.f);
        o.y = fmaxf(o.y, 0.f);
        o.z = fmaxf(o.z, 0.f);
        o.w = fmaxf(o.w, 0.f);
    }
    ((float4*)out)[node * 16 + j] = o;
}

// ---------------- launch ----------------
extern "C" void kernel_launch(void* const* d_in, const int* in_sizes, int n_in,
                              void* d_out, int out_size) {
    const float* x      = (const float*)d_in[0];   // (N, D)
    const float* Ws     = (const float*)d_in[1];   // (L, D, D)
    const float* bs     = (const float*)d_in[2];   // (L, D)
    const float* gammas = (const float*)d_in[3];   // (L, D)
    const float* betas  = (const float*)d_in[4];   // (L, D)
    const int*   ei     = (const int*)d_in[5];     // (2, E)
    float* outp = (float*)d_out;

    float* d_hw;
    float* d_h;
    void*  d_deg;
    cudaGetSymbolAddress((void**)&d_hw, g_hw);
    cudaGetSymbolAddress((void**)&d_h, g_h);
    cudaGetSymbolAddress(&d_deg, g_deg);

    const int TB = 256;
    const int gE = (EE + TB - 1) / TB;
    const int gGemm = (NN + 63) / 64;
    const int gAgg = NN / 16;

    // CSR build (once per launch, shared by all layers)
    cudaMemsetAsync(d_deg, 0, NN_PAD * sizeof(int));
    k_count<<<gE, TB>>>(ei);
    k_bsum<<<NBLK, 256>>>();
    k_bscan<<<1, 128>>>();
    k_bscan_fill<<<NBLK, 256>>>();
    k_fill<<<gE, TB>>>(ei);

    // layer 0: x -> g_h
    k_gemm<<<gGemm, TB>>>(x, Ws + 0 * DD * DD, d_hw);
    k_agg<<<gAgg, TB>>>(d_hw, bs + 0 * DD, gammas + 0 * DD, betas + 0 * DD, d_h, 1);
    // layer 1: g_h -> g_h
    k_gemm<<<gGemm, TB>>>(d_h, Ws + 1 * DD * DD, d_hw);
    k_agg<<<gAgg, TB>>>(d_hw, bs + 1 * DD, gammas + 1 * DD, betas + 1 * DD, d_h, 1);
    // layer 2: g_h -> out (no relu)
    k_gemm<<<gGemm, TB>>>(d_h, Ws + 2 * DD * DD, d_hw);
    k_agg<<<gAgg, TB>>>(d_hw, bs + 2 * DD, gammas + 2 * DD, betas + 2 * DD, outp, 0);
}